// round 3
// baseline (speedup 1.0000x reference)
#include <cuda_runtime.h>
#include <cuda_bf16.h>

// Problem shapes (fixed for this registry entry)
#define BS  4
#define NPT 8192
#define CH  64
#define MPT 4096
#define KNN 32
#define R2C 0.04f

#define FPS_T 1024
#define PPT   (NPT / FPS_T)   // 8 points per thread
#define BQW   8               // children (warps) per ball-query block

// Scratch: transposed feats (bs, n, c). 4*8192*64*4B = 8 MB.
__device__ float g_feats_t[(size_t)BS * NPT * CH];

// Faithfully-rounded dx^2+dy^2+dz^2 via error-free transforms (all f32 FMA pipe).
// Result is within <1 ulp of the exact value and collides bitwise whenever the
// exact gap between two distances is << 1 ulp -- mimicking the collision
// behavior of the reference's f32 formula so index tie-breaks line up.
__device__ __forceinline__ float dist2_acc(float dx, float dy, float dz)
{
    const float p1 = __fmul_rn(dx, dx);
    const float e1 = __fmaf_rn(dx, dx, -p1);
    const float p2 = __fmul_rn(dy, dy);
    const float e2 = __fmaf_rn(dy, dy, -p2);
    const float p3 = __fmul_rn(dz, dz);
    const float e3 = __fmaf_rn(dz, dz, -p3);
    // TwoSum(p1, p2)
    const float s1  = __fadd_rn(p1, p2);
    const float b1  = __fsub_rn(s1, p1);
    const float t1  = __fadd_rn(__fsub_rn(p1, __fsub_rn(s1, b1)), __fsub_rn(p2, b1));
    // TwoSum(s1, p3)
    const float s2  = __fadd_rn(s1, p3);
    const float b2  = __fsub_rn(s2, s1);
    const float t2  = __fadd_rn(__fsub_rn(s1, __fsub_rn(s2, b2)), __fsub_rn(p3, b2));
    const float err = __fadd_rn(__fadd_rn(__fadd_rn(e1, e2), e3), __fadd_rn(t1, t2));
    return __fadd_rn(s2, err);
}

// ---------------------------------------------------------------------------
// FPS: one CTA per batch. Points + min_d2 register-resident, 2 barriers/iter.
// seed idx 0, emit-then-update, argmax with lowest-index tie-break.
// ---------------------------------------------------------------------------
__global__ void __launch_bounds__(FPS_T, 1)
fps_kernel(const float* __restrict__ xyz, float* __restrict__ child_xyz)
{
    __shared__ float sredv[32];
    __shared__ int   sredi[32];
    __shared__ int   scur;

    const int b    = blockIdx.x;
    const int tid  = threadIdx.x;
    const int lane = tid & 31;
    const int wid  = tid >> 5;

    const float* __restrict__ X  = xyz + (size_t)b * NPT * 3;
    float* __restrict__       OX = child_xyz + (size_t)b * MPT * 3;

    float px[PPT], py[PPT], pz[PPT], md[PPT];
#pragma unroll
    for (int k = 0; k < PPT; k++) {
        const int j = tid + k * FPS_T;
        px[k] = X[3 * j + 0];
        py[k] = X[3 * j + 1];
        pz[k] = X[3 * j + 2];
        md[k] = 1e10f;
    }

    float cx = X[0], cy = X[1], cz = X[2];

    for (int it = 0; it < MPT; it++) {
        if (tid == 0) {
            OX[3 * it + 0] = cx;
            OX[3 * it + 1] = cy;
            OX[3 * it + 2] = cz;
        }
        float bestv = -1.0f;
        int   besti = 0;
#pragma unroll
        for (int k = 0; k < PPT; k++) {
            const float dx = __fsub_rn(px[k], cx);
            const float dy = __fsub_rn(py[k], cy);
            const float dz = __fsub_rn(pz[k], cz);
            const float d2 = dist2_acc(dx, dy, dz);
            const float nm = fminf(md[k], d2);
            md[k] = nm;
            // strict > keeps the lowest index within this thread (k ascending)
            if (nm > bestv) { bestv = nm; besti = tid + k * FPS_T; }
        }
        // warp argmax with lowest-index tie-break
#pragma unroll
        for (int off = 16; off; off >>= 1) {
            const float ov = __shfl_down_sync(0xffffffffu, bestv, off);
            const int   oi = __shfl_down_sync(0xffffffffu, besti, off);
            if (ov > bestv || (ov == bestv && oi < besti)) { bestv = ov; besti = oi; }
        }
        if (lane == 0) { sredv[wid] = bestv; sredi[wid] = besti; }
        __syncthreads();
        if (wid == 0) {
            bestv = sredv[lane];
            besti = sredi[lane];
#pragma unroll
            for (int off = 16; off; off >>= 1) {
                const float ov = __shfl_down_sync(0xffffffffu, bestv, off);
                const int   oi = __shfl_down_sync(0xffffffffu, besti, off);
                if (ov > bestv || (ov == bestv && oi < besti)) { bestv = ov; besti = oi; }
            }
            if (lane == 0) scur = besti;
        }
        __syncthreads();
        const int cur = scur;
        // L1-resident broadcast read (all threads, same address)
        cx = __ldg(X + 3 * cur + 0);
        cy = __ldg(X + 3 * cur + 1);
        cz = __ldg(X + 3 * cur + 2);
    }
}

// ---------------------------------------------------------------------------
// Transpose feats (bs, C, N) -> g_feats_t (bs, N, C), tiled 32x32.
// ---------------------------------------------------------------------------
__global__ void transpose_kernel(const float* __restrict__ feats)
{
    __shared__ float tile[32][33];
    const int b  = blockIdx.z;
    const int n0 = blockIdx.x * 32;
    const int c0 = blockIdx.y * 32;
    const int tx = threadIdx.x;
    const int ty = threadIdx.y;

    const float* __restrict__ F  = feats + (size_t)b * CH * NPT;
    float* __restrict__       FT = g_feats_t + (size_t)b * NPT * CH;

#pragma unroll
    for (int r = ty; r < 32; r += 8)
        tile[r][tx] = F[(size_t)(c0 + r) * NPT + n0 + tx];
    __syncthreads();
#pragma unroll
    for (int r = ty; r < 32; r += 8)
        FT[(size_t)(n0 + r) * CH + c0 + tx] = tile[tx][r];
}

// ---------------------------------------------------------------------------
// Fused ball query (first-K-within-radius, ascending index) + grouped max.
// One warp per child; each lane owns 2 channels for the max.
// ---------------------------------------------------------------------------
__global__ void __launch_bounds__(BQW * 32)
bq_group_kernel(const float* __restrict__ xyz,
                const float* __restrict__ child_xyz,
                float* __restrict__ out_feats)
{
    __shared__ int   nidx[BQW][KNN];
    __shared__ float sfeat[CH][BQW];

    const int b    = blockIdx.y;
    const int j0   = blockIdx.x * BQW;
    const int w    = threadIdx.x >> 5;
    const int lane = threadIdx.x & 31;
    const int j    = j0 + w;

    const float* __restrict__ X = xyz + (size_t)b * NPT * 3;
    const float cx = child_xyz[((size_t)b * MPT + j) * 3 + 0];
    const float cy = child_xyz[((size_t)b * MPT + j) * 3 + 1];
    const float cz = child_xyz[((size_t)b * MPT + j) * 3 + 2];

    int cnt = 0;
    for (int base = 0; base < NPT; base += 32) {
        const int p = base + lane;
        const float dx = __fsub_rn(X[3 * p + 0], cx);
        const float dy = __fsub_rn(X[3 * p + 1], cy);
        const float dz = __fsub_rn(X[3 * p + 2], cz);
        const float d2 = dist2_acc(dx, dy, dz);
        const bool in = (d2 <= R2C);
        const unsigned mask = __ballot_sync(0xffffffffu, in);
        const int pos = cnt + __popc(mask & ((1u << lane) - 1u));
        if (in && pos < KNN) nidx[w][pos] = p;
        cnt += __popc(mask);
        if (cnt >= KNN) break;   // warp-uniform
    }
    if (cnt == 0) { if (lane == 0) nidx[w][0] = 0; cnt = 1; }
    const int kmax = cnt < KNN ? cnt : KNN;
    __syncwarp();

    const float* __restrict__ FT = g_feats_t + (size_t)b * NPT * CH;
    float m0 = -3.4e38f, m1 = -3.4e38f;
    for (int k = 0; k < kmax; k++) {
        const int p = nidx[w][k];                 // LDS broadcast
        const float2 v = *(const float2*)(FT + (size_t)p * CH + lane * 2);
        m0 = fmaxf(m0, v.x);
        m1 = fmaxf(m1, v.y);
    }
    sfeat[lane * 2 + 0][w] = m0;
    sfeat[lane * 2 + 1][w] = m1;
    __syncthreads();

    // coalesced staged store of (C x BQW) block
    for (int t = threadIdx.x; t < CH * BQW; t += BQW * 32) {
        const int c  = t >> 3;          // / BQW
        const int jj = t & (BQW - 1);
        out_feats[((size_t)b * CH + c) * MPT + j0 + jj] = sfeat[c][jj];
    }
}

// ---------------------------------------------------------------------------
extern "C" void kernel_launch(void* const* d_in, const int* in_sizes, int n_in,
                              void* d_out, int out_size)
{
    const float* xyz   = (const float*)d_in[0];
    const float* feats = (const float*)d_in[1];

    float* out         = (float*)d_out;
    float* child_xyz   = out;                              // (bs, m, 3)
    float* child_feats = out + (size_t)BS * MPT * 3;       // (bs, C, m)

    transpose_kernel<<<dim3(NPT / 32, CH / 32, BS), dim3(32, 8)>>>(feats);
    fps_kernel<<<BS, FPS_T>>>(xyz, child_xyz);
    bq_group_kernel<<<dim3(MPT / BQW, BS), BQW * 32>>>(xyz, child_xyz, child_feats);
}

// round 4
// speedup vs baseline: 1.0137x; 1.0137x over previous
#include <cuda_runtime.h>
#include <cuda_bf16.h>

// Problem shapes (fixed for this registry entry)
#define BS  4
#define NPT 8192
#define CH  64
#define MPT 4096
#define KNN 32
#define R2C 0.04f

#define FPS_T 1024
#define PPT   (NPT / FPS_T)   // 8 points per thread -> 4 packed pairs
#define NPAIR (PPT / 2)
#define BQW   8               // children (warps) per ball-query block

typedef unsigned long long u64;

// Scratch: transposed feats (bs, n, c). 4*8192*64*4B = 8 MB.
__device__ float g_feats_t[(size_t)BS * NPT * CH];

// ---------------------------------------------------------------------------
// Packed f32x2 primitives (sm_100a). Per-lane IEEE RN, bit-identical to scalar.
// ---------------------------------------------------------------------------
__device__ __forceinline__ u64 pk2(float lo, float hi)
{
    u64 r; asm("mov.b64 %0, {%1, %2};" : "=l"(r) : "f"(lo), "f"(hi)); return r;
}
__device__ __forceinline__ void upk2(u64 v, float& lo, float& hi)
{
    asm("mov.b64 {%0, %1}, %2;" : "=f"(lo), "=f"(hi) : "l"(v));
}
__device__ __forceinline__ u64 addx2(u64 a, u64 b)
{
    u64 r; asm("add.rn.f32x2 %0, %1, %2;" : "=l"(r) : "l"(a), "l"(b)); return r;
}
__device__ __forceinline__ u64 mulx2(u64 a, u64 b)
{
    u64 r; asm("mul.rn.f32x2 %0, %1, %2;" : "=l"(r) : "l"(a), "l"(b)); return r;
}
__device__ __forceinline__ u64 fmx2(u64 a, u64 b, u64 c)
{
    u64 r; asm("fma.rn.f32x2 %0, %1, %2, %3;" : "=l"(r) : "l"(a), "l"(b), "l"(c)); return r;
}
// exact sign flip (ALU pipe, off the binding fma pipe)
__device__ __forceinline__ u64 negx2(u64 a) { return a ^ 0x8000000080000000ULL; }
// RN(a-b) via fma(b,-1,a): single rounding of exact a-b == sub.rn, bit-identical
#define NEG1X2 0xBF800000BF800000ULL
__device__ __forceinline__ u64 subx2(u64 a, u64 b) { return fmx2(b, NEG1X2, a); }

// Faithfully-rounded dx^2+dy^2+dz^2, packed pair. Same EFT sequence (same
// rounding events, same bits per lane) as the scalar dist2_acc below.
__device__ __forceinline__ u64 dist2x2(u64 dx, u64 dy, u64 dz)
{
    const u64 p1 = mulx2(dx, dx);
    const u64 e1 = fmx2(dx, dx, negx2(p1));
    const u64 p2 = mulx2(dy, dy);
    const u64 e2 = fmx2(dy, dy, negx2(p2));
    const u64 p3 = mulx2(dz, dz);
    const u64 e3 = fmx2(dz, dz, negx2(p3));
    const u64 s1 = addx2(p1, p2);
    const u64 b1 = subx2(s1, p1);
    const u64 t1 = addx2(subx2(p1, subx2(s1, b1)), subx2(p2, b1));
    const u64 s2 = addx2(s1, p3);
    const u64 b2 = subx2(s2, s1);
    const u64 t2 = addx2(subx2(s1, subx2(s2, b2)), subx2(p3, b2));
    const u64 err = addx2(addx2(addx2(e1, e2), e3), addx2(t1, t2));
    return addx2(s2, err);
}

// Scalar version (ball query) -- identical rounding sequence.
__device__ __forceinline__ float dist2_acc(float dx, float dy, float dz)
{
    const float p1 = __fmul_rn(dx, dx);
    const float e1 = __fmaf_rn(dx, dx, -p1);
    const float p2 = __fmul_rn(dy, dy);
    const float e2 = __fmaf_rn(dy, dy, -p2);
    const float p3 = __fmul_rn(dz, dz);
    const float e3 = __fmaf_rn(dz, dz, -p3);
    const float s1  = __fadd_rn(p1, p2);
    const float b1  = __fsub_rn(s1, p1);
    const float t1  = __fadd_rn(__fsub_rn(p1, __fsub_rn(s1, b1)), __fsub_rn(p2, b1));
    const float s2  = __fadd_rn(s1, p3);
    const float b2  = __fsub_rn(s2, s1);
    const float t2  = __fadd_rn(__fsub_rn(s1, __fsub_rn(s2, b2)), __fsub_rn(p3, b2));
    const float err = __fadd_rn(__fadd_rn(__fadd_rn(e1, e2), e3), __fadd_rn(t1, t2));
    return __fadd_rn(s2, err);
}

// ---------------------------------------------------------------------------
// FPS: one CTA per batch. Packed-pair distance math on the f32x2 fma pipe.
// seed idx 0, emit-then-update, argmax with lowest-index tie-break.
// ---------------------------------------------------------------------------
__global__ void __launch_bounds__(FPS_T, 1)
fps_kernel(const float* __restrict__ xyz, float* __restrict__ child_xyz)
{
    __shared__ float sredv[32];
    __shared__ int   sredi[32];
    __shared__ int   scur;

    const int b    = blockIdx.x;
    const int tid  = threadIdx.x;
    const int lane = tid & 31;
    const int wid  = tid >> 5;

    const float* __restrict__ X  = xyz + (size_t)b * NPT * 3;
    float* __restrict__       OX = child_xyz + (size_t)b * MPT * 3;

    // pair p holds points k=2p (lo) and k=2p+1 (hi); index = tid + k*FPS_T
    u64 pxp[NPAIR], pyp[NPAIR], pzp[NPAIR];
    float md[PPT];
#pragma unroll
    for (int p = 0; p < NPAIR; p++) {
        const int j0 = tid + (2 * p) * FPS_T;
        const int j1 = tid + (2 * p + 1) * FPS_T;
        pxp[p] = pk2(X[3 * j0 + 0], X[3 * j1 + 0]);
        pyp[p] = pk2(X[3 * j0 + 1], X[3 * j1 + 1]);
        pzp[p] = pk2(X[3 * j0 + 2], X[3 * j1 + 2]);
    }
#pragma unroll
    for (int k = 0; k < PPT; k++) md[k] = 1e10f;

    float cx = X[0], cy = X[1], cz = X[2];

    for (int it = 0; it < MPT; it++) {
        if (tid == 0) {
            OX[3 * it + 0] = cx;
            OX[3 * it + 1] = cy;
            OX[3 * it + 2] = cz;
        }
        // px - cx computed as px + (-cx): -cx exact, add.rn == sub.rn bits
        const u64 ncx = pk2(-cx, -cx);
        const u64 ncy = pk2(-cy, -cy);
        const u64 ncz = pk2(-cz, -cz);

        float bestv = -1.0f;
        int   besti = 0;
#pragma unroll
        for (int p = 0; p < NPAIR; p++) {
            const u64 dx = addx2(pxp[p], ncx);
            const u64 dy = addx2(pyp[p], ncy);
            const u64 dz = addx2(pzp[p], ncz);
            float d2lo, d2hi;
            upk2(dist2x2(dx, dy, dz), d2lo, d2hi);

            const float nm0 = fminf(md[2 * p + 0], d2lo);
            md[2 * p + 0] = nm0;
            if (nm0 > bestv) { bestv = nm0; besti = tid + (2 * p) * FPS_T; }
            const float nm1 = fminf(md[2 * p + 1], d2hi);
            md[2 * p + 1] = nm1;
            if (nm1 > bestv) { bestv = nm1; besti = tid + (2 * p + 1) * FPS_T; }
        }
        // warp argmax with lowest-index tie-break
#pragma unroll
        for (int off = 16; off; off >>= 1) {
            const float ov = __shfl_down_sync(0xffffffffu, bestv, off);
            const int   oi = __shfl_down_sync(0xffffffffu, besti, off);
            if (ov > bestv || (ov == bestv && oi < besti)) { bestv = ov; besti = oi; }
        }
        if (lane == 0) { sredv[wid] = bestv; sredi[wid] = besti; }
        __syncthreads();
        if (wid == 0) {
            bestv = sredv[lane];
            besti = sredi[lane];
#pragma unroll
            for (int off = 16; off; off >>= 1) {
                const float ov = __shfl_down_sync(0xffffffffu, bestv, off);
                const int   oi = __shfl_down_sync(0xffffffffu, besti, off);
                if (ov > bestv || (ov == bestv && oi < besti)) { bestv = ov; besti = oi; }
            }
            if (lane == 0) scur = besti;
        }
        __syncthreads();
        const int cur = scur;
        // L1-resident broadcast read (all threads, same address)
        cx = __ldg(X + 3 * cur + 0);
        cy = __ldg(X + 3 * cur + 1);
        cz = __ldg(X + 3 * cur + 2);
    }
}

// ---------------------------------------------------------------------------
// Transpose feats (bs, C, N) -> g_feats_t (bs, N, C), tiled 32x32.
// ---------------------------------------------------------------------------
__global__ void transpose_kernel(const float* __restrict__ feats)
{
    __shared__ float tile[32][33];
    const int b  = blockIdx.z;
    const int n0 = blockIdx.x * 32;
    const int c0 = blockIdx.y * 32;
    const int tx = threadIdx.x;
    const int ty = threadIdx.y;

    const float* __restrict__ F  = feats + (size_t)b * CH * NPT;
    float* __restrict__       FT = g_feats_t + (size_t)b * NPT * CH;

#pragma unroll
    for (int r = ty; r < 32; r += 8)
        tile[r][tx] = F[(size_t)(c0 + r) * NPT + n0 + tx];
    __syncthreads();
#pragma unroll
    for (int r = ty; r < 32; r += 8)
        FT[(size_t)(n0 + r) * CH + c0 + tx] = tile[tx][r];
}

// ---------------------------------------------------------------------------
// Fused ball query (first-K-within-radius, ascending index) + grouped max.
// One warp per child; each lane owns 2 channels for the max.
// ---------------------------------------------------------------------------
__global__ void __launch_bounds__(BQW * 32)
bq_group_kernel(const float* __restrict__ xyz,
                const float* __restrict__ child_xyz,
                float* __restrict__ out_feats)
{
    __shared__ int   nidx[BQW][KNN];
    __shared__ float sfeat[CH][BQW];

    const int b    = blockIdx.y;
    const int j0   = blockIdx.x * BQW;
    const int w    = threadIdx.x >> 5;
    const int lane = threadIdx.x & 31;
    const int j    = j0 + w;

    const float* __restrict__ X = xyz + (size_t)b * NPT * 3;
    const float cx = child_xyz[((size_t)b * MPT + j) * 3 + 0];
    const float cy = child_xyz[((size_t)b * MPT + j) * 3 + 1];
    const float cz = child_xyz[((size_t)b * MPT + j) * 3 + 2];

    int cnt = 0;
    for (int base = 0; base < NPT; base += 32) {
        const int p = base + lane;
        const float dx = __fsub_rn(X[3 * p + 0], cx);
        const float dy = __fsub_rn(X[3 * p + 1], cy);
        const float dz = __fsub_rn(X[3 * p + 2], cz);
        const float d2 = dist2_acc(dx, dy, dz);
        const bool in = (d2 <= R2C);
        const unsigned mask = __ballot_sync(0xffffffffu, in);
        const int pos = cnt + __popc(mask & ((1u << lane) - 1u));
        if (in && pos < KNN) nidx[w][pos] = p;
        cnt += __popc(mask);
        if (cnt >= KNN) break;   // warp-uniform
    }
    if (cnt == 0) { if (lane == 0) nidx[w][0] = 0; cnt = 1; }
    const int kmax = cnt < KNN ? cnt : KNN;
    __syncwarp();

    const float* __restrict__ FT = g_feats_t + (size_t)b * NPT * CH;
    float m0 = -3.4e38f, m1 = -3.4e38f;
    for (int k = 0; k < kmax; k++) {
        const int p = nidx[w][k];                 // LDS broadcast
        const float2 v = *(const float2*)(FT + (size_t)p * CH + lane * 2);
        m0 = fmaxf(m0, v.x);
        m1 = fmaxf(m1, v.y);
    }
    sfeat[lane * 2 + 0][w] = m0;
    sfeat[lane * 2 + 1][w] = m1;
    __syncthreads();

    // coalesced staged store of (C x BQW) block
    for (int t = threadIdx.x; t < CH * BQW; t += BQW * 32) {
        const int c  = t >> 3;          // / BQW
        const int jj = t & (BQW - 1);
        out_feats[((size_t)b * CH + c) * MPT + j0 + jj] = sfeat[c][jj];
    }
}

// ---------------------------------------------------------------------------
extern "C" void kernel_launch(void* const* d_in, const int* in_sizes, int n_in,
                              void* d_out, int out_size)
{
    const float* xyz   = (const float*)d_in[0];
    const float* feats = (const float*)d_in[1];

    float* out         = (float*)d_out;
    float* child_xyz   = out;                              // (bs, m, 3)
    float* child_feats = out + (size_t)BS * MPT * 3;       // (bs, C, m)

    transpose_kernel<<<dim3(NPT / 32, CH / 32, BS), dim3(32, 8)>>>(feats);
    fps_kernel<<<BS, FPS_T>>>(xyz, child_xyz);
    bq_group_kernel<<<dim3(MPT / BQW, BS), BQW * 32>>>(xyz, child_xyz, child_feats);
}